// round 16
// baseline (speedup 1.0000x reference)
#include <cuda_runtime.h>
#include <math.h>
#include <stdint.h>

#define NB   32      // batch
#define NT   4096    // sequence
#define NCAT 128
#define NNE  512
#define NHS  64

#define CHR  8                        // rows per chunk (16 KB)
#define CPB  16                       // chunks per block (single-wave grid)
#define NBPB 32                       // blocks per batch = NT/(CHR*CPB)
#define CHUNK_BYTES (CHR * NNE * 4)   // 16384

// ---- scratch (device globals; no allocations allowed) ----
__device__ float g_qk[NB * NNE];
__device__ float g_pm[NB * NBPB];
__device__ float g_ps[NB * NBPB];
__device__ float g_pacc[(size_t)NB * NBPB * NNE];  // 2 MB
__device__ float g_y[NB * NNE];

// ============================================================
// Kernel A: q = cat_emb@Wq ; qk[n] = 0.125 * Wk[n,:]·q
// ============================================================
__global__ void kA(const float* __restrict__ cat_emb,
                   const float* __restrict__ Wq,
                   const float* __restrict__ Wk) {
    const int b = blockIdx.x;
    const int tid = threadIdx.x;
    const int h = tid & 63;
    const int part = tid >> 6;

    __shared__ float qpart[8][NHS];
    __shared__ float qs[NHS];

    float a = 0.f;
    const float* ce = cat_emb + b * NCAT;
    #pragma unroll
    for (int c = part * 16; c < part * 16 + 16; ++c)
        a += ce[c] * Wq[c * NHS + h];
    qpart[part][h] = a;
    __syncthreads();

    if (tid < NHS) {
        float q = 0.f;
        #pragma unroll
        for (int p = 0; p < 8; ++p) q += qpart[p][tid];
        qs[tid] = q * 0.125f;
    }
    __syncthreads();

    const float4* wk4 = reinterpret_cast<const float4*>(Wk + tid * NHS);
    const float4* q4  = reinterpret_cast<const float4*>(qs);
    float acc = 0.f;
    #pragma unroll
    for (int i = 0; i < 16; ++i) {
        const float4 w = wk4[i];
        const float4 qq = q4[i];
        acc += w.x * qq.x + w.y * qq.y + w.z * qq.z + w.w * qq.w;
    }
    g_qk[b * NNE + tid] = acc;
}

// ============================================================
// TMA / mbarrier helpers
// ============================================================
__device__ __forceinline__ void bulk_copy(uint32_t dst_smem, const float* src,
                                          uint32_t mbar) {
    asm volatile("mbarrier.arrive.expect_tx.shared.b64 _, [%0], %1;"
                 :: "r"(mbar), "r"((uint32_t)CHUNK_BYTES) : "memory");
    asm volatile(
        "cp.async.bulk.shared::cluster.global.mbarrier::complete_tx::bytes "
        "[%0], [%1], %2, [%3];"
        :: "r"(dst_smem), "l"(src), "r"((uint32_t)CHUNK_BYTES), "r"(mbar)
        : "memory");
}

__device__ __forceinline__ void mbar_wait(uint32_t mbar, uint32_t parity) {
    uint32_t done;
    asm volatile(
        "{\n\t.reg .pred p;\n\t"
        "mbarrier.try_wait.parity.acquire.cta.shared::cta.b64 p, [%1], %2;\n\t"
        "selp.b32 %0, 1, 0, p;\n\t}"
        : "=r"(done) : "r"(mbar), "r"(parity) : "memory");
    while (!done) {
        asm volatile(
            "{\n\t.reg .pred p;\n\t"
            "mbarrier.try_wait.parity.acquire.cta.shared::cta.b64 p, [%1], %2, 0x989680;\n\t"
            "selp.b32 %0, 1, 0, p;\n\t}"
            : "=r"(done) : "r"(mbar), "r"(parity) : "memory");
    }
}

__device__ __forceinline__ void mbar_arrive(uint32_t mbar) {
    asm volatile("mbarrier.arrive.shared.b64 _, [%0];" :: "r"(mbar) : "memory");
}

// ============================================================
// Fused kernel v11: warp-autonomous chunks, zero per-chunk block barriers.
// Warp w owns row w of every chunk: computes its score, keeps private
// running (M,S) and a private full-width 512-col accumulator
// (16 floats/lane). Buffer release via empty mbarrier (count=8);
// warp 0 lane 0 waits empties and issues refills. One block-wide
// combine at the end (reuses dead ring smem).
// grid: (NBPB, NB), 256 threads (8 warps), 32 KB ring.
// ============================================================
__global__ void __launch_bounds__(256) kFuse11(const float* __restrict__ x) {
    const int b = blockIdx.y;
    const int blk = blockIdx.x;
    const int tid = threadIdx.x;
    const int warp = tid >> 5, lane = tid & 31;

    __shared__ __align__(128) float sx[2][CHR * NNE];   // 32 KB (ring; reused)
    __shared__ float sM[8], sS[8];
    __shared__ __align__(8) unsigned long long full_b[2], empty_b[2];

    uint32_t sx_a[2], full_a[2], empty_a[2];
    #pragma unroll
    for (int i = 0; i < 2; ++i) {
        sx_a[i]   = (uint32_t)__cvta_generic_to_shared(sx[i]);
        full_a[i] = (uint32_t)__cvta_generic_to_shared(&full_b[i]);
        empty_a[i]= (uint32_t)__cvta_generic_to_shared(&empty_b[i]);
    }

    const float* xbase = x + ((size_t)b * NT + (size_t)blk * CHR * CPB) * NNE;

    if (tid == 0) {
        asm volatile("mbarrier.init.shared.b64 [%0], 1;" :: "r"(full_a[0]) : "memory");
        asm volatile("mbarrier.init.shared.b64 [%0], 1;" :: "r"(full_a[1]) : "memory");
        asm volatile("mbarrier.init.shared.b64 [%0], 8;" :: "r"(empty_a[0]) : "memory");
        asm volatile("mbarrier.init.shared.b64 [%0], 8;" :: "r"(empty_a[1]) : "memory");
        asm volatile("fence.proxy.async.shared::cta;" ::: "memory");
    }
    __syncthreads();

    if (tid == 0) {
        bulk_copy(sx_a[0], xbase,                     full_a[0]);
        bulk_copy(sx_a[1], xbase + (size_t)CHR * NNE, full_a[1]);
    }

    // qk slice for this warp's row layout: lane covers float4s lane+32i
    const float4* qkp = reinterpret_cast<const float4*>(g_qk + b * NNE);
    float4 qv[4];
    #pragma unroll
    for (int i = 0; i < 4; ++i) qv[i] = qkp[lane + 32 * i];

    float M = -INFINITY, S = 0.f;
    float4 acc[4];
    #pragma unroll
    for (int i = 0; i < 4; ++i) acc[i] = make_float4(0.f, 0.f, 0.f, 0.f);

    #pragma unroll
    for (int c = 0; c < CPB; ++c) {
        const int buf = c & 1;
        const uint32_t par = (c >> 1) & 1;
        mbar_wait(full_a[buf], par);

        // this warp's row of the chunk
        const float4* row4 = reinterpret_cast<const float4*>(
            sx[buf] + warp * NNE);
        float4 xv[4];
        #pragma unroll
        for (int i = 0; i < 4; ++i) xv[i] = row4[lane + 32 * i];

        // score
        float d = 0.f;
        #pragma unroll
        for (int i = 0; i < 4; ++i)
            d += xv[i].x * qv[i].x + xv[i].y * qv[i].y +
                 xv[i].z * qv[i].z + xv[i].w * qv[i].w;
        #pragma unroll
        for (int o = 16; o > 0; o >>= 1)
            d += __shfl_xor_sync(0xffffffffu, d, o);

        // private online-softmax update
        const float newM = fmaxf(M, d);
        const float f = __expf(M - newM);   // 0 on first chunk
        const float w = __expf(d - newM);
        S = S * f + w;
        #pragma unroll
        for (int i = 0; i < 4; ++i) {
            acc[i].x = fmaf(w, xv[i].x, acc[i].x * f);
            acc[i].y = fmaf(w, xv[i].y, acc[i].y * f);
            acc[i].z = fmaf(w, xv[i].z, acc[i].z * f);
            acc[i].w = fmaf(w, xv[i].w, acc[i].w * f);
        }
        M = newM;

        // release buffer (warp-local)
        __syncwarp();
        if (lane == 0) mbar_arrive(empty_a[buf]);

        // warp 0 refills chunk c+2 once all 8 warps released buf
        if (warp == 0 && lane == 0 && c + 2 < CPB) {
            mbar_wait(empty_a[buf], par);
            bulk_copy(sx_a[buf], xbase + (size_t)(c + 2) * CHR * NNE,
                      full_a[buf]);
        }
    }

    // ---- one-time block combine (ring is dead; reuse sx[0]) ----
    __syncthreads();
    float* scomb = sx[0];                 // 8 x 512 floats = 16 KB
    float4* aw4 = reinterpret_cast<float4*>(scomb + warp * NNE);
    #pragma unroll
    for (int i = 0; i < 4; ++i) aw4[lane + 32 * i] = acc[i];
    if (lane == 0) { sM[warp] = M; sS[warp] = S; }
    __syncthreads();

    float mb = sM[0];
    #pragma unroll
    for (int w2 = 1; w2 < 8; ++w2) mb = fmaxf(mb, sM[w2]);

    float a0 = 0.f, a1 = 0.f, Sb = 0.f;
    #pragma unroll
    for (int w2 = 0; w2 < 8; ++w2) {
        const float f = __expf(sM[w2] - mb);
        Sb += sS[w2] * f;
        a0 = fmaf(scomb[w2 * NNE + tid],       f, a0);
        a1 = fmaf(scomb[w2 * NNE + tid + 256], f, a1);
    }

    float* p = g_pacc + (size_t)(b * NBPB + blk) * NNE;
    p[tid]       = a0;
    p[tid + 256] = a1;
    if (tid == 0) {
        g_pm[b * NBPB + blk] = mb;
        g_ps[b * NBPB + blk] = Sb;
    }
}

// ============================================================
// Kernel E: combine 32 partials (8-way float4) -> xa; xa@Wv; @Wp; LayerNorm
// grid: NB, 1024 threads
// ============================================================
__global__ void kE(const float* __restrict__ Wv,
                   const float* __restrict__ Wp,
                   const float* __restrict__ gamma,
                   const float* __restrict__ beta) {
    const int b = blockIdx.x;
    const int tid = threadIdx.x;
    const int warp = tid >> 5, lane = tid & 31;

    __shared__ float spm[NBPB], sps[NBPB], sf[NBPB];
    __shared__ float4 xpart[8][NNE / 4];
    __shared__ float xa[NNE];
    __shared__ float wpart[16][NHS];
    __shared__ float outh[NHS];
    __shared__ float red[32];
    __shared__ float bcast;

    if (tid < NBPB) {
        spm[tid] = g_pm[b * NBPB + tid];
        sps[tid] = g_ps[b * NBPB + tid];
    }
    __syncthreads();

    float mb = -INFINITY;
    #pragma unroll
    for (int c = 0; c < NBPB; ++c) mb = fmaxf(mb, spm[c]);

    if (tid < NBPB) sf[tid] = __expf(spm[tid] - mb);
    __syncthreads();

    float Sb = 0.f;
    #pragma unroll
    for (int c = 0; c < NBPB; ++c) Sb += sps[c] * sf[c];

    {
        const int col4 = tid & 127;
        const int part = tid >> 7;        // 8 parts x 4 partials
        const float4* pp = reinterpret_cast<const float4*>(
            g_pacc + (size_t)(b * NBPB + part * 4) * NNE);
        const float* f = sf + part * 4;
        float4 a = make_float4(0.f, 0.f, 0.f, 0.f);
        #pragma unroll
        for (int c = 0; c < 4; ++c) {
            const float4 v = pp[(size_t)c * 128 + col4];
            const float fc = f[c];
            a.x = fmaf(v.x, fc, a.x);
            a.y = fmaf(v.y, fc, a.y);
            a.z = fmaf(v.z, fc, a.z);
            a.w = fmaf(v.w, fc, a.w);
        }
        xpart[part][col4] = a;
    }
    __syncthreads();
    if (tid < 128) {
        float4 a = xpart[0][tid];
        #pragma unroll
        for (int p = 1; p < 8; ++p) {
            const float4 v = xpart[p][tid];
            a.x += v.x; a.y += v.y; a.z += v.z; a.w += v.w;
        }
        const float inv = 1.f / Sb;
        reinterpret_cast<float4*>(xa)[tid] =
            make_float4(a.x * inv, a.y * inv, a.z * inv, a.w * inv);
    }
    __syncthreads();

    {
        const int h = tid & 63;
        const int part = tid >> 6;
        float po = 0.f;
        #pragma unroll
        for (int n = part * 32; n < part * 32 + 32; ++n)
            po = fmaf(xa[n], Wv[n * NHS + h], po);
        wpart[part][h] = po;
    }
    __syncthreads();
    if (tid < NHS) {
        float o = 0.f;
        #pragma unroll
        for (int p = 0; p < 16; ++p) o += wpart[p][tid];
        outh[tid] = o;
    }
    __syncthreads();

    float y = 0.f;
    if (tid < NNE) {
        #pragma unroll
        for (int h2 = 0; h2 < NHS; ++h2)
            y = fmaf(outh[h2], Wp[h2 * NNE + tid], y);
    }

    float s = (tid < NNE) ? y : 0.f;
    #pragma unroll
    for (int o = 16; o > 0; o >>= 1)
        s += __shfl_xor_sync(0xffffffffu, s, o);
    if (lane == 0) red[warp] = s;
    __syncthreads();
    if (tid < 32) {
        float ss2 = red[tid];
        #pragma unroll
        for (int o = 16; o > 0; o >>= 1)
            ss2 += __shfl_xor_sync(0xffffffffu, ss2, o);
        if (tid == 0) bcast = ss2;
    }
    __syncthreads();
    const float mu = bcast * (1.f / NNE);
    __syncthreads();

    const float d = (tid < NNE) ? (y - mu) : 0.f;
    float vs = d * d;
    #pragma unroll
    for (int o = 16; o > 0; o >>= 1)
        vs += __shfl_xor_sync(0xffffffffu, vs, o);
    if (lane == 0) red[warp] = vs;
    __syncthreads();
    if (tid < 32) {
        float ss2 = red[tid];
        #pragma unroll
        for (int o = 16; o > 0; o >>= 1)
            ss2 += __shfl_xor_sync(0xffffffffu, ss2, o);
        if (tid == 0) bcast = ss2;
    }
    __syncthreads();
    const float var = bcast * (1.f / NNE);
    const float rstd = rsqrtf(var + 1e-5f);

    if (tid < NNE)
        g_y[b * NNE + tid] = d * rstd * gamma[tid] + beta[tid];
}

// ============================================================
// Kernel F: broadcast g_y[b,:] to out[b, t, :]; streaming float4 stores
// ============================================================
#define ROWS_F 64
__global__ void kF(float* __restrict__ out) {
    const int b = blockIdx.y;
    const int tid = threadIdx.x;
    const int col = tid & 127;
    const int half = tid >> 7;

    const float4 val = reinterpret_cast<const float4*>(g_y + b * NNE)[col];

    const int t0 = blockIdx.x * ROWS_F;
    float4* o = reinterpret_cast<float4*>(out + ((size_t)b * NT + t0) * NNE);
    #pragma unroll 8
    for (int r = 0; r < ROWS_F / 2; ++r)
        __stcs(&o[(size_t)(r * 2 + half) * (NNE / 4) + col], val);
}

// ============================================================
extern "C" void kernel_launch(void* const* d_in, const int* in_sizes, int n_in,
                              void* d_out, int out_size) {
    const float* x       = (const float*)d_in[0];
    const float* cat_emb = (const float*)d_in[1];
    const float* Wq      = (const float*)d_in[2];
    const float* Wk      = (const float*)d_in[3];
    const float* Wv      = (const float*)d_in[4];
    const float* Wp      = (const float*)d_in[5];
    const float* gamma   = (const float*)d_in[6];
    const float* beta    = (const float*)d_in[7];
    float* out = (float*)d_out;

    kA<<<NB, 512>>>(cat_emb, Wq, Wk);
    kFuse11<<<dim3(NBPB, NB), 256>>>(x);
    kE<<<NB, 1024>>>(Wv, Wp, gamma, beta);
    kF<<<dim3(NT / ROWS_F, NB), 256>>>(out);
}